// round 1
// baseline (speedup 1.0000x reference)
#include <cuda_runtime.h>

#define B_ 2
#define T_ 192
#define C_ 512
#define H_ 8
#define D_ 64
#define PROJC (5 * C_)  // 2560

// scratch (device globals; no allocation allowed)
__device__ float g_proj[B_ * T_ * PROJC];   // (B*T, 2560)
__device__ float g_attn[B_ * T_ * C_];      // (B*T, 512)  attention output, heads merged

// ---------------------------------------------------------------------------
// Generic tiled GEMM + bias: C[M,N] = A[M,K] @ Bm[K,N] + bias[N]
// 64x64 tile, 256 threads, 4x4 register microtile, K-tile 16.
// M,N divisible by 64; K divisible by 16 (holds for both uses).
// ---------------------------------------------------------------------------
__global__ __launch_bounds__(256) void gemm_bias_kernel(
    const float* __restrict__ A, const float* __restrict__ Bm,
    const float* __restrict__ bias, float* __restrict__ C,
    int M, int N, int K)
{
    __shared__ float AsT[16][65];   // transposed A tile, padded
    __shared__ float Bs[16][64];

    const int t  = threadIdx.x;
    const int tx = t & 15;
    const int ty = t >> 4;
    const int row0 = blockIdx.y * 64;
    const int col0 = blockIdx.x * 64;

    float acc[4][4] = {};

    for (int kt = 0; kt < K; kt += 16) {
        // load A tile 64x16 (coalesced float4), store transposed
        {
            int r  = t >> 2;          // 0..63
            int c4 = (t & 3) << 2;    // 0,4,8,12
            float4 av = *(const float4*)&A[(size_t)(row0 + r) * K + kt + c4];
            AsT[c4 + 0][r] = av.x;
            AsT[c4 + 1][r] = av.y;
            AsT[c4 + 2][r] = av.z;
            AsT[c4 + 3][r] = av.w;
        }
        // load B tile 16x64 (coalesced float4)
        {
            int r  = t >> 4;          // 0..15
            int c4 = (t & 15) << 2;
            *(float4*)&Bs[r][c4] = *(const float4*)&Bm[(size_t)(kt + r) * N + col0 + c4];
        }
        __syncthreads();

        #pragma unroll
        for (int kk = 0; kk < 16; kk++) {
            float a[4];
            #pragma unroll
            for (int r = 0; r < 4; r++) a[r] = AsT[kk][(ty << 2) + r];
            float4 bv = *(float4*)&Bs[kk][tx << 2];
            float bb[4] = {bv.x, bv.y, bv.z, bv.w};
            #pragma unroll
            for (int r = 0; r < 4; r++)
                #pragma unroll
                for (int c = 0; c < 4; c++)
                    acc[r][c] += a[r] * bb[c];
        }
        __syncthreads();
    }

    #pragma unroll
    for (int r = 0; r < 4; r++) {
        float4 o;
        int col = col0 + (tx << 2);
        o.x = acc[r][0] + bias[col + 0];
        o.y = acc[r][1] + bias[col + 1];
        o.z = acc[r][2] + bias[col + 2];
        o.w = acc[r][3] + bias[col + 3];
        *(float4*)&C[(size_t)(row0 + (ty << 2) + r) * N + col] = o;
    }
}

// ---------------------------------------------------------------------------
// Fused two-simplicial attention.
// One block per (b, h, i-tile of 8). 256 threads (8 warps; warp w owns i=w).
// Per j-tile of 8 (24 phases):
//   PT[d][m]   = q_i[d]*k1_j[d]          (m = i*8+jj, 64x64)
//   S[m][k]    = sum_d PT[d][m]*K2T[d][k]       GEMM 64x192x64
//   online softmax per i (warp-local), E written transposed ET[k][m]
//   U[m][d]    = sum_k ET[k][m]*V2[k][d]        GEMM 64x64x192
//   acc[i][d]  = acc*alpha_i + sum_jj v1_jj[d]*U[(i,jj)][d]
// Final: out[i][d] = acc[i][d] / Z_i
// ---------------------------------------------------------------------------

// shared memory layout (floats)
#define OFF_Q    0        // 512   Qs[8][64] (prescaled by D^-0.5)
#define OFF_K1   512      // 512   K1s[8][64]
#define OFF_V1   1024     // 512   V1s[8][64]
#define OFF_ACC  1536     // 512   acc[8][64]
#define OFF_K2T  2048     // 12288 K2T[64][192]
#define OFF_V2   14336    // 12288 V2s[192][64]
#define OFF_PT   26624    // 4096  PT[64][64]
#define OFF_ET   30720    // 13056 ET[192][68]  (also staging [192][65] at init)
#define OFF_M    43776    // 8
#define OFF_Z    43784    // 8
#define OFF_AL   43792    // 8
#define SMEM_FLOATS 43800

__global__ __launch_bounds__(256, 1) void attn_kernel(
    const float* __restrict__ proj, float* __restrict__ outp)
{
    extern __shared__ float sm[];
    float* Qs   = sm + OFF_Q;
    float* K1s  = sm + OFF_K1;
    float* V1s  = sm + OFF_V1;
    float* accS = sm + OFF_ACC;
    float* K2T  = sm + OFF_K2T;
    float* V2s  = sm + OFF_V2;
    float* PT   = sm + OFF_PT;
    float* ET   = sm + OFF_ET;
    float* sM   = sm + OFF_M;
    float* sZ   = sm + OFF_Z;
    float* sAl  = sm + OFF_AL;

    const int t    = threadIdx.x;
    const int tx   = t & 15;
    const int ty   = t >> 4;
    const int warp = t >> 5;      // == i within tile
    const int lane = t & 31;
    const int b    = blockIdx.z;
    const int h    = blockIdx.y;
    const int i0   = blockIdx.x * 8;

    const float* base = proj + (size_t)b * T_ * PROJC + h * D_;
    // column offsets within a proj row: q:0, k1:C_, v1:2C_, k2:3C_, v2:4C_

    // ---- init: Q (scaled), acc, M/Z, V2, stage K2 ----
    for (int idx = t; idx < 512; idx += 256) {
        int r = idx >> 6, d = idx & 63;
        Qs[idx]   = base[(size_t)(i0 + r) * PROJC + d] * 0.125f;  // D^-0.5
        accS[idx] = 0.f;
    }
    if (t < 8) { sM[t] = -3.0e38f; sZ[t] = 0.f; sAl[t] = 0.f; }
    for (int idx = t; idx < T_ * D_; idx += 256) {
        int k = idx >> 6, d = idx & 63;
        V2s[idx]        = base[(size_t)k * PROJC + 4 * C_ + d];
        ET[k * 65 + d]  = base[(size_t)k * PROJC + 3 * C_ + d];  // staging for K2
    }
    __syncthreads();
    // transpose K2 staging -> K2T[d][k] (conflict-free both directions)
    for (int idx = t; idx < T_ * D_; idx += 256) {
        int d = idx / T_, k = idx - d * T_;
        K2T[d * T_ + k] = ET[k * 65 + d];
    }
    __syncthreads();

    for (int jt = 0; jt < T_; jt += 8) {
        // ---- load K1/V1 rows for this j-tile (float4, coalesced) ----
        {
            int tt = t & 127;
            int jj = tt >> 4, d4 = (tt & 15) << 2;
            const float* src = base + (size_t)(jt + jj) * PROJC +
                               (t < 128 ? C_ : 2 * C_) + d4;
            float* dst = (t < 128 ? K1s : V1s) + jj * 64 + d4;
            *(float4*)dst = *(const float4*)src;
        }
        __syncthreads();

        // ---- PT[d][m] = Qs[i][d] * K1s[jj][d] ----
        #pragma unroll
        for (int l = 0; l < 16; l++) {
            int idx = t + l * 256;        // idx = d*64 + m
            int d = idx >> 6, m = idx & 63;
            PT[idx] = Qs[((m >> 3) << 6) + d] * K1s[((m & 7) << 6) + d];
        }
        __syncthreads();

        // ---- GEMM1: S[m][k], m = ty*4+r, k = p*64 + tx*4 + c ----
        float s[3][4][4] = {};
        #pragma unroll 4
        for (int d = 0; d < 64; d++) {
            float4 af = *(float4*)&PT[(d << 6) + (ty << 2)];
            float a[4] = {af.x, af.y, af.z, af.w};
            #pragma unroll
            for (int p = 0; p < 3; p++) {
                float4 bf = *(float4*)&K2T[d * T_ + p * 64 + (tx << 2)];
                float bb[4] = {bf.x, bf.y, bf.z, bf.w};
                #pragma unroll
                for (int r = 0; r < 4; r++)
                    #pragma unroll
                    for (int c = 0; c < 4; c++)
                        s[p][r][c] += a[r] * bb[c];
            }
        }

        // ---- online softmax (warp-local: warp w holds all of i=w) ----
        float mloc = -3.0e38f;
        #pragma unroll
        for (int p = 0; p < 3; p++)
            #pragma unroll
            for (int r = 0; r < 4; r++)
                #pragma unroll
                for (int c = 0; c < 4; c++)
                    mloc = fmaxf(mloc, s[p][r][c]);
        #pragma unroll
        for (int off = 16; off > 0; off >>= 1)
            mloc = fmaxf(mloc, __shfl_xor_sync(0xffffffffu, mloc, off));

        float Mold  = sM[warp];
        float Mnew  = fmaxf(Mold, mloc);
        float alpha = __expf(Mold - Mnew);
        float lsum  = 0.f;
        #pragma unroll
        for (int p = 0; p < 3; p++)
            #pragma unroll
            for (int c = 0; c < 4; c++) {
                float4 ev;
                ev.x = __expf(s[p][0][c] - Mnew);
                ev.y = __expf(s[p][1][c] - Mnew);
                ev.z = __expf(s[p][2][c] - Mnew);
                ev.w = __expf(s[p][3][c] - Mnew);
                lsum += (ev.x + ev.y) + (ev.z + ev.w);
                int k = p * 64 + (tx << 2) + c;
                *(float4*)&ET[k * 68 + (ty << 2)] = ev;   // E transposed
            }
        #pragma unroll
        for (int off = 16; off > 0; off >>= 1)
            lsum += __shfl_xor_sync(0xffffffffu, lsum, off);
        if (lane == 0) {
            sZ[warp]  = sZ[warp] * alpha + lsum;
            sM[warp]  = Mnew;
            sAl[warp] = alpha;
        }
        __syncthreads();

        // ---- GEMM2: U[m][d] = sum_k ET[k][m]*V2s[k][d] ----
        float u[4][4] = {};
        #pragma unroll 4
        for (int k = 0; k < T_; k++) {
            float4 af = *(float4*)&ET[k * 68 + (ty << 2)];
            float4 bf = *(float4*)&V2s[(k << 6) + (tx << 2)];
            float a[4]  = {af.x, af.y, af.z, af.w};
            float bb[4] = {bf.x, bf.y, bf.z, bf.w};
            #pragma unroll
            for (int r = 0; r < 4; r++)
                #pragma unroll
                for (int c = 0; c < 4; c++)
                    u[r][c] += a[r] * bb[c];
        }

        // ---- epilogue: acc[i][d] = acc*alpha + sum_jj v1[jj][d]*U[(i,jj)][d] ----
        float contrib[4] = {0.f, 0.f, 0.f, 0.f};
        #pragma unroll
        for (int r = 0; r < 4; r++) {
            int jj = ((ty & 1) << 2) + r;
            #pragma unroll
            for (int c = 0; c < 4; c++)
                contrib[c] += V1s[(jj << 6) + (tx << 2) + c] * u[r][c];
        }
        #pragma unroll
        for (int c = 0; c < 4; c++)
            contrib[c] += __shfl_xor_sync(0xffffffffu, contrib[c], 16);
        if (lane < 16) {
            float al = sAl[warp];
            #pragma unroll
            for (int c = 0; c < 4; c++) {
                int ai = (warp << 6) + (tx << 2) + c;
                accS[ai] = accS[ai] * al + contrib[c];
            }
        }
        __syncthreads();
    }

    // ---- finalize: out[i][d] = acc/Z ----
    if (lane < 16) {
        float invZ = 1.0f / sZ[warp];
        int d4 = tx << 2;
        float4 o;
        o.x = accS[(warp << 6) + d4 + 0] * invZ;
        o.y = accS[(warp << 6) + d4 + 1] * invZ;
        o.z = accS[(warp << 6) + d4 + 2] * invZ;
        o.w = accS[(warp << 6) + d4 + 3] * invZ;
        *(float4*)&outp[(size_t)(b * T_ + i0 + warp) * C_ + h * D_ + d4] = o;
    }
}

// ---------------------------------------------------------------------------
extern "C" void kernel_launch(void* const* d_in, const int* in_sizes, int n_in,
                              void* d_out, int out_size)
{
    const float* x     = (const float*)d_in[0];
    const float* W_in  = (const float*)d_in[1];
    const float* b_in  = (const float*)d_in[2];
    const float* W_out = (const float*)d_in[3];
    const float* b_out = (const float*)d_in[4];
    float* y = (float*)d_out;

    float *proj, *attn;
    cudaGetSymbolAddress((void**)&proj, g_proj);
    cudaGetSymbolAddress((void**)&attn, g_attn);

    const size_t SMEM = (size_t)SMEM_FLOATS * sizeof(float);  // 175,200 B
    cudaFuncSetAttribute(attn_kernel,
                         cudaFuncAttributeMaxDynamicSharedMemorySize, (int)SMEM);

    // 1) proj = x @ W_in + b_in : (384,512)@(512,2560)
    dim3 g1(PROJC / 64, (B_ * T_) / 64);
    gemm_bias_kernel<<<g1, 256>>>(x, W_in, b_in, proj, B_ * T_, PROJC, C_);

    // 2) fused two-simplicial attention
    dim3 ga(T_ / 8, H_, B_);
    attn_kernel<<<ga, 256, SMEM>>>(proj, attn);

    // 3) y = attn @ W_out + b_out : (384,512)@(512,512)
    dim3 g2(C_ / 64, (B_ * T_) / 64);
    gemm_bias_kernel<<<g2, 256>>>(attn, W_out, b_out, y, B_ * T_, C_, C_);
}